// round 11
// baseline (speedup 1.0000x reference)
#include <cuda_runtime.h>
#include <math.h>

#define NN 8192
#define HH 128
#define NRELC 90
#define NBB 8
#define SII 16
#define EMAX 131072
#define ECHUNK 16
#define NBLK 128

typedef unsigned long long ull;

// ---------------- scratch (static device globals; no allocation) ----------------
__device__ float g_h[NN * HH];
__device__ float g_h2[NN * HH];
__device__ float g_zml[NN * 2 * HH];
__device__ float g_z[NN * HH];
__device__ float g_U[NN * HH];
__device__ float g_h3[NN * HH];
__device__ float g_V[NN * HH];
__device__ float g_S[HH * HH];
__device__ float g_S2[HH * HH];
__device__ int   g_blkcnt[NBLK * NRELC];
__device__ int   g_blkbase[NBLK * NRELC];
__device__ int   g_off[NRELC + 1];
__device__ int   g_perm[EMAX];

// vectorized fp32 atomic add (sm_90+)
__device__ __forceinline__ void red4(float* p, float a, float b, float c, float d) {
    asm volatile("red.global.add.v4.f32 [%0], {%1,%2,%3,%4};"
                 :: "l"(p), "f"(a), "f"(b), "f"(c), "f"(d) : "memory");
}
__device__ __forceinline__ void fma2(ull& d, ull a, ull b) {
    asm volatile("fma.rn.f32x2 %0, %1, %2, %0;" : "+l"(d) : "l"(a), "l"(b));
}
__device__ __forceinline__ ull pack2(float x) {
    ull r; asm("mov.b64 %0, {%1, %1};" : "=l"(r) : "f"(x)); return r;
}
__device__ __forceinline__ void unpack2(ull v, float& a, float& b) {
    asm("mov.b64 {%0, %1}, %2;" : "=f"(a), "=f"(b) : "l"(v));
}

// ---------------- tf32 helpers ----------------
__device__ __forceinline__ void tf32split(float x, unsigned& hi, unsigned& lo) {
    asm("cvt.rna.tf32.f32 %0, %1;" : "=r"(hi) : "f"(x));
    float l = x - __uint_as_float(hi);
    asm("cvt.rna.tf32.f32 %0, %1;" : "=r"(lo) : "f"(l));
}
__device__ __forceinline__ void mma_tf32(float* c, unsigned a0, unsigned a1,
                                         unsigned a2, unsigned a3,
                                         unsigned b0, unsigned b1) {
    asm volatile("mma.sync.aligned.m16n8k8.row.col.f32.tf32.tf32.f32 "
                 "{%0,%1,%2,%3}, {%4,%5,%6,%7}, {%8,%9}, {%0,%1,%2,%3};"
                 : "+f"(c[0]), "+f"(c[1]), "+f"(c[2]), "+f"(c[3])
                 : "r"(a0), "r"(a1), "r"(a2), "r"(a3), "r"(b0), "r"(b1));
}

// ---------------- counting sort pass 1: per-block histogram ----------------
__global__ void k_hist(const int* __restrict__ et, int E) {
    __shared__ int sh[NRELC];
    for (int i = threadIdx.x; i < NRELC; i += blockDim.x) sh[i] = 0;
    __syncthreads();
    int per = (E + NBLK - 1) / NBLK;
    int b0 = blockIdx.x * per, b1 = min(E, b0 + per);
    for (int i = b0 + threadIdx.x; i < b1; i += blockDim.x)
        atomicAdd(&sh[et[i]], 1);
    __syncthreads();
    for (int i = threadIdx.x; i < NRELC; i += blockDim.x)
        g_blkcnt[blockIdx.x * NRELC + i] = sh[i];
}

__global__ void k_scan(int E) {
    __shared__ int stot[NRELC];
    __shared__ int sbase[NRELC];
    int r = threadIdx.x;
    if (r < NRELC) {
        int tot = 0;
        #pragma unroll 4
        for (int b = 0; b < NBLK; b++) tot += g_blkcnt[b * NRELC + r];
        stot[r] = tot;
    }
    __syncthreads();
    if (r < NRELC) {
        int acc = 0;
        for (int i = 0; i < r; i++) acc += stot[i];
        sbase[r] = acc;
        g_off[r] = acc;
        if (r == NRELC - 1) g_off[NRELC] = E;
    }
    __syncthreads();
    if (r < NRELC) {
        int run = sbase[r];
        #pragma unroll 4
        for (int b = 0; b < NBLK; b++) {
            g_blkbase[b * NRELC + r] = run;
            run += g_blkcnt[b * NRELC + r];
        }
    }
}

__global__ void k_scatter(const int* __restrict__ et, int E) {
    __shared__ int sloc[NRELC];
    for (int i = threadIdx.x; i < NRELC; i += blockDim.x)
        sloc[i] = g_blkbase[blockIdx.x * NRELC + i];
    __syncthreads();
    int per = (E + NBLK - 1) / NBLK;
    int b0 = blockIdx.x * per, b1 = min(E, b0 + per);
    for (int i = b0 + threadIdx.x; i < b1; i += blockDim.x) {
        int p = atomicAdd(&sloc[et[i]], 1);
        g_perm[p] = i;
    }
}

// ---------------- zero fill ----------------
__global__ void k_zero(float4* p, int n4) {
    int i = blockIdx.x * blockDim.x + threadIdx.x;
    if (i < n4) p[i] = make_float4(0.f, 0.f, 0.f, 0.f);
}

// ---------------- edge compute core ----------------
__device__ __forceinline__ void edge_do(float4 xv, int d, float nr, int relu_in,
                                        const ull* w01, const ull* w23,
                                        int b, int o0, int lane,
                                        float* __restrict__ acc_out) {
    float4 xr = xv;
    if (relu_in) {
        xr.x = fmaxf(xr.x, 0.f); xr.y = fmaxf(xr.y, 0.f);
        xr.z = fmaxf(xr.z, 0.f); xr.w = fmaxf(xr.w, 0.f);
    }
    ull a01 = 0ull, a23 = 0ull;
    #pragma unroll
    for (int c = 0; c < 4; c++) {
        int sl = b * 4 + c;
        float4 xi;
        xi.x = __shfl_sync(0xffffffffu, xr.x, sl);
        xi.y = __shfl_sync(0xffffffffu, xr.y, sl);
        xi.z = __shfl_sync(0xffffffffu, xr.z, sl);
        xi.w = __shfl_sync(0xffffffffu, xr.w, sl);
        ull p0 = pack2(xi.x), p1 = pack2(xi.y), p2 = pack2(xi.z), p3 = pack2(xi.w);
        fma2(a01, p0, w01[c * 4 + 0]); fma2(a23, p0, w23[c * 4 + 0]);
        fma2(a01, p1, w01[c * 4 + 1]); fma2(a23, p1, w23[c * 4 + 1]);
        fma2(a01, p2, w01[c * 4 + 2]); fma2(a23, p2, w23[c * 4 + 2]);
        fma2(a01, p3, w01[c * 4 + 3]); fma2(a23, p3, w23[c * 4 + 3]);
    }
    float a0, a1, a2, a3;
    unpack2(a01, a0, a1);
    unpack2(a23, a2, a3);
    red4(acc_out + (size_t)d * HH + lane * 4, a0 * nr, a1 * nr, a2 * nr, a3 * nr);
}

// ---------------- RGCN edge messages ----------------
__global__ void __launch_bounds__(256)
k_edges_sorted(const float* __restrict__ x, const int* __restrict__ src,
               const int* __restrict__ dst, const float* __restrict__ norm,
               const float* __restrict__ W, float* __restrict__ acc_out,
               int relu_in) {
    __shared__ float sW[NBB * SII * SII];
    int rel = blockIdx.y;
    const float4* Wr = (const float4*)(W + rel * 2048);
    for (int i = threadIdx.x; i < 512; i += blockDim.x) ((float4*)sW)[i] = Wr[i];
    __syncthreads();

    int lane = threadIdx.x & 31;
    int warp = threadIdx.x >> 5;
    int b  = lane >> 2;
    int o0 = (lane & 3) * 4;

    ull w01[SII], w23[SII];
    #pragma unroll
    for (int i = 0; i < SII; i++) {
        int idx = b * 256 + i * 16 + o0;
        w01[i] = *(const ull*)&sW[idx];
        w23[i] = *(const ull*)&sW[idx + 2];
    }

    int off0 = g_off[rel];
    int len  = g_off[rel + 1] - off0;
    int start = off0 + (int)(((long long)len * blockIdx.x) / ECHUNK);
    int end   = off0 + (int)(((long long)len * (blockIdx.x + 1)) / ECHUNK);
    const int stride = 16;

    int i = start + warp * 2;

    int dA = 0, dB = 0; float nrA = 0.f, nrB = 0.f;
    float4 xvA = make_float4(0.f, 0.f, 0.f, 0.f);
    float4 xvB = xvA;
    if (i < end) {
        int e = g_perm[i];
        int s = src[e];  dA = dst[e];  nrA = norm[e];
        xvA = ((const float4*)(x + (size_t)s * HH))[lane];
    }
    if (i + 1 < end) {
        int e = g_perm[i + 1];
        int s = src[e];  dB = dst[e];  nrB = norm[e];
        xvB = ((const float4*)(x + (size_t)s * HH))[lane];
    }

    while (i < end) {
        int inext = i + stride;
        int dA2 = 0, dB2 = 0; float nrA2 = 0.f, nrB2 = 0.f;
        float4 xvA2 = make_float4(0.f, 0.f, 0.f, 0.f);
        float4 xvB2 = xvA2;
        if (inext < end) {
            int e = g_perm[inext];
            int s = src[e];  dA2 = dst[e];  nrA2 = norm[e];
            xvA2 = ((const float4*)(x + (size_t)s * HH))[lane];
        }
        if (inext + 1 < end) {
            int e = g_perm[inext + 1];
            int s = src[e];  dB2 = dst[e];  nrB2 = norm[e];
            xvB2 = ((const float4*)(x + (size_t)s * HH))[lane];
        }

        edge_do(xvA, dA, nrA, relu_in, w01, w23, b, o0, lane, acc_out);
        if (i + 1 < end)
            edge_do(xvB, dB, nrB, relu_in, w01, w23, b, o0, lane, acc_out);

        i = inext;
        dA = dA2; nrA = nrA2; xvA = xvA2;
        dB = dB2; nrB = nrB2; xvB = xvB2;
    }
}

// ---------------- tf32 TC GEMM, split-on-stage, 512 threads ----------------------
// CTA tile 64 rows x 128 cols; 16 warps (4m x 4n: 16 rows x 32 cols each).
// B staged fp32 from global, hi/lo split ONCE into smem during staging.
// smem: sA 64x132 fp32 (33.8KB) + sBhi/sBlo 128x136 u32 (2x69.6KB) = 169KB, 1 CTA/SM.
#define ASTR 132
#define BSTR 136
__global__ void __launch_bounds__(512)
k_gemm_tc(const float* __restrict__ A, const float* __restrict__ B,
          const float* __restrict__ add1, const float* __restrict__ bias,
          float* __restrict__ C, int Hout, int reluA) {
    extern __shared__ float sm[];
    float*    sA   = sm;                                  // 64*132
    unsigned* sBhi = (unsigned*)(sm + 64 * ASTR);         // 128*136
    unsigned* sBlo = sBhi + 128 * BSTR;                   // 128*136
    int t = threadIdx.x;
    int row0 = blockIdx.x * 64;
    int col0 = blockIdx.y * 128;

    // stage A (64x128 fp32): 4 float4 per thread
    #pragma unroll
    for (int p = 0; p < 4; p++) {
        int idx = t + p * 512;          // float4 over 64x32
        int r = idx >> 5, c4 = idx & 31;
        float4 v = *(const float4*)&A[(size_t)(row0 + r) * HH + c4 * 4];
        if (reluA) {
            v.x = fmaxf(v.x, 0.f); v.y = fmaxf(v.y, 0.f);
            v.z = fmaxf(v.z, 0.f); v.w = fmaxf(v.w, 0.f);
        }
        *(float4*)&sA[r * ASTR + c4 * 4] = v;
    }
    // stage+split B (128x128): 8 float4 per thread, split once here
    #pragma unroll
    for (int p = 0; p < 8; p++) {
        int idx = t + p * 512;
        int r = idx >> 5, c4 = idx & 31;
        float4 v = *(const float4*)&B[(size_t)r * Hout + col0 + c4 * 4];
        uint4 hi, lo;
        tf32split(v.x, hi.x, lo.x);
        tf32split(v.y, hi.y, lo.y);
        tf32split(v.z, hi.z, lo.z);
        tf32split(v.w, hi.w, lo.w);
        *(uint4*)&sBhi[r * BSTR + c4 * 4] = hi;
        *(uint4*)&sBlo[r * BSTR + c4 * 4] = lo;
    }
    __syncthreads();

    int lane = t & 31;
    int g = lane >> 2, tt = lane & 3;
    int warp = t >> 5;
    int wm = warp >> 2;      // 0..3  (16 rows each)
    int wn = warp & 3;       // 0..3  (32 cols each)

    float c[4][4];
    #pragma unroll
    for (int i = 0; i < 4; i++)
        #pragma unroll
        for (int j = 0; j < 4; j++) c[i][j] = 0.f;

    const float* pa0 = &sA[(wm * 16 + g) * ASTR];
    const float* pa1 = pa0 + 8 * ASTR;

    #pragma unroll 4
    for (int k0 = 0; k0 < 128; k0 += 8) {
        unsigned ah[4], al[4];
        tf32split(pa0[k0 + tt],     ah[0], al[0]);
        tf32split(pa1[k0 + tt],     ah[1], al[1]);
        tf32split(pa0[k0 + tt + 4], ah[2], al[2]);
        tf32split(pa1[k0 + tt + 4], ah[3], al[3]);
        #pragma unroll
        for (int nf = 0; nf < 4; nf++) {
            int cn = wn * 32 + nf * 8 + g;
            unsigned bh0 = sBhi[(k0 + tt) * BSTR + cn];
            unsigned bh1 = sBhi[(k0 + tt + 4) * BSTR + cn];
            unsigned bl0 = sBlo[(k0 + tt) * BSTR + cn];
            unsigned bl1 = sBlo[(k0 + tt + 4) * BSTR + cn];
            mma_tf32(c[nf], ah[0], ah[1], ah[2], ah[3], bh0, bh1);
            mma_tf32(c[nf], ah[0], ah[1], ah[2], ah[3], bl0, bl1);
            mma_tf32(c[nf], al[0], al[1], al[2], al[3], bh0, bh1);
        }
    }

    int r0 = row0 + wm * 16 + g;
    int r1 = r0 + 8;
    #pragma unroll
    for (int nf = 0; nf < 4; nf++) {
        int cb = col0 + wn * 32 + nf * 8 + 2 * tt;
        float bv0 = bias ? bias[cb] : 0.f;
        float bv1 = bias ? bias[cb + 1] : 0.f;
        size_t i0 = (size_t)r0 * Hout + cb;
        size_t i1 = (size_t)r1 * Hout + cb;
        float v00 = c[nf][0] + bv0, v01 = c[nf][1] + bv1;
        float v10 = c[nf][2] + bv0, v11 = c[nf][3] + bv1;
        if (add1) {
            float2 a0 = *(const float2*)&add1[i0];
            float2 a1 = *(const float2*)&add1[i1];
            v00 += a0.x; v01 += a0.y; v10 += a1.x; v11 += a1.y;
        }
        *(float2*)&C[i0] = make_float2(v00, v01);
        *(float2*)&C[i1] = make_float2(v10, v11);
    }
}

// ---------------- S[128,128] += A^T @ B over 64-row chunk ----------------
__global__ void k_atb2(const float* __restrict__ A, const float* __restrict__ Bm,
                       float* __restrict__ S) {
    __shared__ float sA[16][128];
    __shared__ float sB[16][128];
    int t = threadIdx.x;
    int jx = t & 15, iy = t >> 4;
    float acc[8][8];
    #pragma unroll
    for (int i = 0; i < 8; i++)
        #pragma unroll
        for (int j = 0; j < 8; j++) acc[i][j] = 0.f;

    int n0 = blockIdx.x * 64;
    for (int st = 0; st < 4; st++) {
        int nb = n0 + st * 16;
        #pragma unroll
        for (int p = 0; p < 2; p++) {
            int idx = t + p * 256;
            int r = idx >> 5, f4 = idx & 31;
            *(float4*)&sA[r][f4 * 4] = *(const float4*)&A[(size_t)(nb + r) * HH + f4 * 4];
            *(float4*)&sB[r][f4 * 4] = *(const float4*)&Bm[(size_t)(nb + r) * HH + f4 * 4];
        }
        __syncthreads();
        #pragma unroll 4
        for (int n = 0; n < 16; n++) {
            float4 a0 = *(float4*)&sA[n][iy * 8];
            float4 a1 = *(float4*)&sA[n][iy * 8 + 4];
            float4 b0 = *(float4*)&sB[n][jx * 8];
            float4 b1 = *(float4*)&sB[n][jx * 8 + 4];
            float av[8] = {a0.x, a0.y, a0.z, a0.w, a1.x, a1.y, a1.z, a1.w};
            float bw[8] = {b0.x, b0.y, b0.z, b0.w, b1.x, b1.y, b1.z, b1.w};
            #pragma unroll
            for (int i = 0; i < 8; i++)
                #pragma unroll
                for (int j = 0; j < 8; j++) acc[i][j] += av[i] * bw[j];
        }
        __syncthreads();
    }

    #pragma unroll
    for (int i = 0; i < 8; i++) {
        float* p = S + (size_t)(iy * 8 + i) * HH + jx * 8;
        red4(p,     acc[i][0], acc[i][1], acc[i][2], acc[i][3]);
        red4(p + 4, acc[i][4], acc[i][5], acc[i][6], acc[i][7]);
    }
}

// ---------------- z = mean + exp(log_std) * eps ----------------
__global__ void k_zcomb(const float* __restrict__ zml, const float* __restrict__ eps,
                        float* __restrict__ z) {
    int i = blockIdx.x * blockDim.x + threadIdx.x;
    int n = i >> 7, c = i & 127;
    z[i] = zml[n * 256 + c] + expf(zml[n * 256 + 128 + c]) * eps[i];
}

// ---------------- host ----------------
extern "C" void kernel_launch(void* const* d_in, const int* in_sizes, int n_in,
                              void* d_out, int out_size) {
    const int*   src   = (const int*)d_in[1];
    const int*   dst   = (const int*)d_in[2];
    const int*   et    = (const int*)d_in[3];
    const float* norm  = (const float*)d_in[4];
    const float* eps   = (const float*)d_in[5];
    const float* emb   = (const float*)d_in[6];   // node_ids = arange(N) -> x0 = embedding
    const float* W0    = (const float*)d_in[7];
    const float* loop0 = (const float*)d_in[8];
    const float* b0    = (const float*)d_in[9];
    const float* W1    = (const float*)d_in[10];
    const float* loop1 = (const float*)d_in[11];
    const float* b1    = (const float*)d_in[12];
    const float* Wz    = (const float*)d_in[13];
    const float* bz    = (const float*)d_in[14];
    const float* Wi    = (const float*)d_in[15];
    const float* bi    = (const float*)d_in[16];
    const float* hbi   = (const float*)d_in[17];
    const float* Wo    = (const float*)d_in[18];
    const float* bo    = (const float*)d_in[19];
    const float* hbo   = (const float*)d_in[20];
    int E = in_sizes[1];

    float *h, *h2, *zml, *z, *U, *h3, *V, *S, *S2;
    cudaGetSymbolAddress((void**)&h,    g_h);
    cudaGetSymbolAddress((void**)&h2,   g_h2);
    cudaGetSymbolAddress((void**)&zml,  g_zml);
    cudaGetSymbolAddress((void**)&z,    g_z);
    cudaGetSymbolAddress((void**)&U,    g_U);
    cudaGetSymbolAddress((void**)&h3,   g_h3);
    cudaGetSymbolAddress((void**)&V,    g_V);
    cudaGetSymbolAddress((void**)&S,    g_S);
    cudaGetSymbolAddress((void**)&S2,   g_S2);

    float* out = (float*)d_out;
    dim3 egrid(ECHUNK, NRELC);
    const int GSMEM = (64 * ASTR + 2 * 128 * BSTR) * 4;   // 173056 B = 169KB
    cudaFuncSetAttribute(k_gemm_tc, cudaFuncAttributeMaxDynamicSharedMemorySize, GSMEM);
    dim3 tg1(NN / 64, 1), tg2(NN / 64, 2);

    // 1-3: counting sort by relation
    k_hist<<<NBLK, 256>>>(et, E);
    k_scan<<<1, 128>>>(E);
    k_scatter<<<NBLK, 256>>>(et, E);

    // 4: h = emb@loop0 + b0        (launch #4: profiled)
    k_gemm_tc<<<tg1, 512, GSMEM>>>(emb, loop0, nullptr, b0, h, 128, 0);
    k_edges_sorted<<<egrid, 256>>>(emb, src, dst, norm, W0, h, 0);

    // layer 1
    k_gemm_tc<<<tg1, 512, GSMEM>>>(h, loop1, nullptr, b1, h2, 128, 1);
    k_edges_sorted<<<egrid, 256>>>(h, src, dst, norm, W1, h2, 1);

    // VAE head
    k_gemm_tc<<<tg2, 512, GSMEM>>>(h2, Wz, nullptr, bz, zml, 256, 0);
    k_zcomb<<<NN * HH / 256, 256>>>(zml, eps, z);

    // decode 1: h3 = z @ (z^T @ (z@Wi + bi + emb)) + hbi
    k_gemm_tc<<<tg1, 512, GSMEM>>>(z, Wi, emb, bi, U, 128, 0);
    k_zero<<<(HH * HH / 4 + 255) / 256, 256>>>((float4*)S, HH * HH / 4);
    k_atb2<<<NN / 64, 256>>>(z, U, S);
    k_gemm_tc<<<tg1, 512, GSMEM>>>(z, S, nullptr, hbi, h3, 128, 0);

    // decode 2: out = h3 @ (h3^T @ (h3@Wo + bo + emb)) + hbo
    k_gemm_tc<<<tg1, 512, GSMEM>>>(h3, Wo, emb, bo, V, 128, 0);
    k_zero<<<(HH * HH / 4 + 255) / 256, 256>>>((float4*)S2, HH * HH / 4);
    k_atb2<<<NN / 64, 256>>>(h3, V, S2);
    k_gemm_tc<<<tg1, 512, GSMEM>>>(h3, S2, nullptr, hbo, out, 128, 0);
}

// round 12
// speedup vs baseline: 1.0329x; 1.0329x over previous
#include <cuda_runtime.h>
#include <math.h>

#define NN 8192
#define HH 128
#define NRELC 90
#define NBB 8
#define SII 16
#define EMAX 131072
#define ECHUNK 16
#define NBLK 128

typedef unsigned long long ull;

// ---------------- scratch (static device globals; no allocation) ----------------
__device__ float g_h[NN * HH];
__device__ float g_h2[NN * HH];
__device__ float g_zml[NN * 2 * HH];
__device__ float g_z[NN * HH];
__device__ float g_U[NN * HH];
__device__ float g_h3[NN * HH];
__device__ float g_V[NN * HH];
__device__ float g_S[HH * HH];
__device__ float g_S2[HH * HH];
__device__ int   g_blkcnt[NBLK * NRELC];
__device__ int   g_blkbase[NBLK * NRELC];
__device__ int   g_off[NRELC + 1];
__device__ int   g_perm[EMAX];

// vectorized fp32 atomic add (sm_90+)
__device__ __forceinline__ void red4(float* p, float a, float b, float c, float d) {
    asm volatile("red.global.add.v4.f32 [%0], {%1,%2,%3,%4};"
                 :: "l"(p), "f"(a), "f"(b), "f"(c), "f"(d) : "memory");
}
__device__ __forceinline__ void fma2(ull& d, ull a, ull b) {
    asm volatile("fma.rn.f32x2 %0, %1, %2, %0;" : "+l"(d) : "l"(a), "l"(b));
}
__device__ __forceinline__ ull pack2(float x) {
    ull r; asm("mov.b64 %0, {%1, %1};" : "=l"(r) : "f"(x)); return r;
}
__device__ __forceinline__ void unpack2(ull v, float& a, float& b) {
    asm("mov.b64 {%0, %1}, %2;" : "=f"(a), "=f"(b) : "l"(v));
}

// ---------------- tf32 helpers ----------------
__device__ __forceinline__ void tf32split(float x, unsigned& hi, unsigned& lo) {
    asm("cvt.rna.tf32.f32 %0, %1;" : "=r"(hi) : "f"(x));
    float l = x - __uint_as_float(hi);
    asm("cvt.rna.tf32.f32 %0, %1;" : "=r"(lo) : "f"(l));
}
__device__ __forceinline__ void mma_tf32(float* c, unsigned a0, unsigned a1,
                                         unsigned a2, unsigned a3,
                                         unsigned b0, unsigned b1) {
    asm volatile("mma.sync.aligned.m16n8k8.row.col.f32.tf32.tf32.f32 "
                 "{%0,%1,%2,%3}, {%4,%5,%6,%7}, {%8,%9}, {%0,%1,%2,%3};"
                 : "+f"(c[0]), "+f"(c[1]), "+f"(c[2]), "+f"(c[3])
                 : "r"(a0), "r"(a1), "r"(a2), "r"(a3), "r"(b0), "r"(b1));
}

// ---------------- counting sort pass 1: per-block histogram ----------------
__global__ void k_hist(const int* __restrict__ et, int E) {
    __shared__ int sh[NRELC];
    for (int i = threadIdx.x; i < NRELC; i += blockDim.x) sh[i] = 0;
    __syncthreads();
    int per = (E + NBLK - 1) / NBLK;
    int b0 = blockIdx.x * per, b1 = min(E, b0 + per);
    for (int i = b0 + threadIdx.x; i < b1; i += blockDim.x)
        atomicAdd(&sh[et[i]], 1);
    __syncthreads();
    for (int i = threadIdx.x; i < NRELC; i += blockDim.x)
        g_blkcnt[blockIdx.x * NRELC + i] = sh[i];
}

__global__ void k_scan(int E) {
    __shared__ int stot[NRELC];
    __shared__ int sbase[NRELC];
    int r = threadIdx.x;
    if (r < NRELC) {
        int tot = 0;
        #pragma unroll 4
        for (int b = 0; b < NBLK; b++) tot += g_blkcnt[b * NRELC + r];
        stot[r] = tot;
    }
    __syncthreads();
    if (r < NRELC) {
        int acc = 0;
        for (int i = 0; i < r; i++) acc += stot[i];
        sbase[r] = acc;
        g_off[r] = acc;
        if (r == NRELC - 1) g_off[NRELC] = E;
    }
    __syncthreads();
    if (r < NRELC) {
        int run = sbase[r];
        #pragma unroll 4
        for (int b = 0; b < NBLK; b++) {
            g_blkbase[b * NRELC + r] = run;
            run += g_blkcnt[b * NRELC + r];
        }
    }
}

__global__ void k_scatter(const int* __restrict__ et, int E) {
    __shared__ int sloc[NRELC];
    for (int i = threadIdx.x; i < NRELC; i += blockDim.x)
        sloc[i] = g_blkbase[blockIdx.x * NRELC + i];
    __syncthreads();
    int per = (E + NBLK - 1) / NBLK;
    int b0 = blockIdx.x * per, b1 = min(E, b0 + per);
    for (int i = b0 + threadIdx.x; i < b1; i += blockDim.x) {
        int p = atomicAdd(&sloc[et[i]], 1);
        g_perm[p] = i;
    }
}

// ---------------- zero fill ----------------
__global__ void k_zero(float4* p, int n4) {
    int i = blockIdx.x * blockDim.x + threadIdx.x;
    if (i < n4) p[i] = make_float4(0.f, 0.f, 0.f, 0.f);
}

// ---------------- edge compute core ----------------
__device__ __forceinline__ void edge_do(float4 xv, int d, float nr, int relu_in,
                                        const ull* w01, const ull* w23,
                                        int b, int o0, int lane,
                                        float* __restrict__ acc_out) {
    float4 xr = xv;
    if (relu_in) {
        xr.x = fmaxf(xr.x, 0.f); xr.y = fmaxf(xr.y, 0.f);
        xr.z = fmaxf(xr.z, 0.f); xr.w = fmaxf(xr.w, 0.f);
    }
    ull a01 = 0ull, a23 = 0ull;
    #pragma unroll
    for (int c = 0; c < 4; c++) {
        int sl = b * 4 + c;
        float4 xi;
        xi.x = __shfl_sync(0xffffffffu, xr.x, sl);
        xi.y = __shfl_sync(0xffffffffu, xr.y, sl);
        xi.z = __shfl_sync(0xffffffffu, xr.z, sl);
        xi.w = __shfl_sync(0xffffffffu, xr.w, sl);
        ull p0 = pack2(xi.x), p1 = pack2(xi.y), p2 = pack2(xi.z), p3 = pack2(xi.w);
        fma2(a01, p0, w01[c * 4 + 0]); fma2(a23, p0, w23[c * 4 + 0]);
        fma2(a01, p1, w01[c * 4 + 1]); fma2(a23, p1, w23[c * 4 + 1]);
        fma2(a01, p2, w01[c * 4 + 2]); fma2(a23, p2, w23[c * 4 + 2]);
        fma2(a01, p3, w01[c * 4 + 3]); fma2(a23, p3, w23[c * 4 + 3]);
    }
    float a0, a1, a2, a3;
    unpack2(a01, a0, a1);
    unpack2(a23, a2, a3);
    red4(acc_out + (size_t)d * HH + lane * 4, a0 * nr, a1 * nr, a2 * nr, a3 * nr);
}

// ---------------- RGCN edge messages ----------------
__global__ void __launch_bounds__(256)
k_edges_sorted(const float* __restrict__ x, const int* __restrict__ src,
               const int* __restrict__ dst, const float* __restrict__ norm,
               const float* __restrict__ W, float* __restrict__ acc_out,
               int relu_in) {
    __shared__ float sW[NBB * SII * SII];
    int rel = blockIdx.y;
    const float4* Wr = (const float4*)(W + rel * 2048);
    for (int i = threadIdx.x; i < 512; i += blockDim.x) ((float4*)sW)[i] = Wr[i];
    __syncthreads();

    int lane = threadIdx.x & 31;
    int warp = threadIdx.x >> 5;
    int b  = lane >> 2;
    int o0 = (lane & 3) * 4;

    ull w01[SII], w23[SII];
    #pragma unroll
    for (int i = 0; i < SII; i++) {
        int idx = b * 256 + i * 16 + o0;
        w01[i] = *(const ull*)&sW[idx];
        w23[i] = *(const ull*)&sW[idx + 2];
    }

    int off0 = g_off[rel];
    int len  = g_off[rel + 1] - off0;
    int start = off0 + (int)(((long long)len * blockIdx.x) / ECHUNK);
    int end   = off0 + (int)(((long long)len * (blockIdx.x + 1)) / ECHUNK);
    const int stride = 16;

    int i = start + warp * 2;

    int dA = 0, dB = 0; float nrA = 0.f, nrB = 0.f;
    float4 xvA = make_float4(0.f, 0.f, 0.f, 0.f);
    float4 xvB = xvA;
    if (i < end) {
        int e = g_perm[i];
        int s = src[e];  dA = dst[e];  nrA = norm[e];
        xvA = ((const float4*)(x + (size_t)s * HH))[lane];
    }
    if (i + 1 < end) {
        int e = g_perm[i + 1];
        int s = src[e];  dB = dst[e];  nrB = norm[e];
        xvB = ((const float4*)(x + (size_t)s * HH))[lane];
    }

    while (i < end) {
        int inext = i + stride;
        int dA2 = 0, dB2 = 0; float nrA2 = 0.f, nrB2 = 0.f;
        float4 xvA2 = make_float4(0.f, 0.f, 0.f, 0.f);
        float4 xvB2 = xvA2;
        if (inext < end) {
            int e = g_perm[inext];
            int s = src[e];  dA2 = dst[e];  nrA2 = norm[e];
            xvA2 = ((const float4*)(x + (size_t)s * HH))[lane];
        }
        if (inext + 1 < end) {
            int e = g_perm[inext + 1];
            int s = src[e];  dB2 = dst[e];  nrB2 = norm[e];
            xvB2 = ((const float4*)(x + (size_t)s * HH))[lane];
        }

        edge_do(xvA, dA, nrA, relu_in, w01, w23, b, o0, lane, acc_out);
        if (i + 1 < end)
            edge_do(xvB, dB, nrB, relu_in, w01, w23, b, o0, lane, acc_out);

        i = inext;
        dA = dA2; nrA = nrA2; xvA = xvA2;
        dB = dB2; nrB = nrB2; xvB = xvB2;
    }
}

// ---------------- tf32 TC GEMM, split-on-stage, 512 thr, reg-pipelined ----------
// CTA tile 64 rows x 128 cols; 16 warps (4m x 4n). Whole K in smem; k-loop fully
// unrolled with register double-buffer: loads for iter k+1 issue before mma of k.
#define ASTR 132
#define BSTR 136
__global__ void __launch_bounds__(512)
k_gemm_tc(const float* __restrict__ A, const float* __restrict__ B,
          const float* __restrict__ add1, const float* __restrict__ bias,
          float* __restrict__ C, int Hout, int reluA) {
    extern __shared__ float sm[];
    float*    sA   = sm;                                  // 64*132
    unsigned* sBhi = (unsigned*)(sm + 64 * ASTR);         // 128*136
    unsigned* sBlo = sBhi + 128 * BSTR;                   // 128*136
    int t = threadIdx.x;
    int row0 = blockIdx.x * 64;
    int col0 = blockIdx.y * 128;

    // stage A (64x128 fp32): 4 float4 per thread
    #pragma unroll
    for (int p = 0; p < 4; p++) {
        int idx = t + p * 512;
        int r = idx >> 5, c4 = idx & 31;
        float4 v = *(const float4*)&A[(size_t)(row0 + r) * HH + c4 * 4];
        if (reluA) {
            v.x = fmaxf(v.x, 0.f); v.y = fmaxf(v.y, 0.f);
            v.z = fmaxf(v.z, 0.f); v.w = fmaxf(v.w, 0.f);
        }
        *(float4*)&sA[r * ASTR + c4 * 4] = v;
    }
    // stage+split B (128x128): 8 float4 per thread
    #pragma unroll
    for (int p = 0; p < 8; p++) {
        int idx = t + p * 512;
        int r = idx >> 5, c4 = idx & 31;
        float4 v = *(const float4*)&B[(size_t)r * Hout + col0 + c4 * 4];
        uint4 hi, lo;
        tf32split(v.x, hi.x, lo.x);
        tf32split(v.y, hi.y, lo.y);
        tf32split(v.z, hi.z, lo.z);
        tf32split(v.w, hi.w, lo.w);
        *(uint4*)&sBhi[r * BSTR + c4 * 4] = hi;
        *(uint4*)&sBlo[r * BSTR + c4 * 4] = lo;
    }
    __syncthreads();

    int lane = t & 31;
    int g = lane >> 2, tt = lane & 3;
    int warp = t >> 5;
    int wm = warp >> 2;      // 0..3  (16 rows each)
    int wn = warp & 3;       // 0..3  (32 cols each)

    float c[4][4];
    #pragma unroll
    for (int i = 0; i < 4; i++)
        #pragma unroll
        for (int j = 0; j < 4; j++) c[i][j] = 0.f;

    const float* pa0 = &sA[(wm * 16 + g) * ASTR];
    const float* pa1 = pa0 + 8 * ASTR;
    int cbase = wn * 32 + g;

    // register double-buffer: B frags [2][16], A floats [2][4]
    unsigned bf[2][16];
    float af[2][4];

    // prologue: load iter 0
    {
        const int k0 = 0;
        af[0][0] = pa0[k0 + tt];     af[0][1] = pa1[k0 + tt];
        af[0][2] = pa0[k0 + tt + 4]; af[0][3] = pa1[k0 + tt + 4];
        #pragma unroll
        for (int nf = 0; nf < 4; nf++) {
            int cn = cbase + nf * 8;
            bf[0][nf * 4 + 0] = sBhi[(k0 + tt) * BSTR + cn];
            bf[0][nf * 4 + 1] = sBhi[(k0 + tt + 4) * BSTR + cn];
            bf[0][nf * 4 + 2] = sBlo[(k0 + tt) * BSTR + cn];
            bf[0][nf * 4 + 3] = sBlo[(k0 + tt + 4) * BSTR + cn];
        }
    }

    #pragma unroll
    for (int it = 0; it < 16; it++) {
        const int cur = it & 1, nxt = cur ^ 1;
        // prefetch iter it+1
        if (it < 15) {
            const int k1 = (it + 1) * 8;
            af[nxt][0] = pa0[k1 + tt];     af[nxt][1] = pa1[k1 + tt];
            af[nxt][2] = pa0[k1 + tt + 4]; af[nxt][3] = pa1[k1 + tt + 4];
            #pragma unroll
            for (int nf = 0; nf < 4; nf++) {
                int cn = cbase + nf * 8;
                bf[nxt][nf * 4 + 0] = sBhi[(k1 + tt) * BSTR + cn];
                bf[nxt][nf * 4 + 1] = sBhi[(k1 + tt + 4) * BSTR + cn];
                bf[nxt][nf * 4 + 2] = sBlo[(k1 + tt) * BSTR + cn];
                bf[nxt][nf * 4 + 3] = sBlo[(k1 + tt + 4) * BSTR + cn];
            }
        }
        // compute iter it
        unsigned ah[4], al[4];
        tf32split(af[cur][0], ah[0], al[0]);
        tf32split(af[cur][1], ah[1], al[1]);
        tf32split(af[cur][2], ah[2], al[2]);
        tf32split(af[cur][3], ah[3], al[3]);
        #pragma unroll
        for (int nf = 0; nf < 4; nf++) {
            unsigned bh0 = bf[cur][nf * 4 + 0];
            unsigned bh1 = bf[cur][nf * 4 + 1];
            unsigned bl0 = bf[cur][nf * 4 + 2];
            unsigned bl1 = bf[cur][nf * 4 + 3];
            mma_tf32(c[nf], ah[0], ah[1], ah[2], ah[3], bh0, bh1);
            mma_tf32(c[nf], ah[0], ah[1], ah[2], ah[3], bl0, bl1);
            mma_tf32(c[nf], al[0], al[1], al[2], al[3], bh0, bh1);
        }
    }

    int r0 = row0 + wm * 16 + g;
    int r1 = r0 + 8;
    #pragma unroll
    for (int nf = 0; nf < 4; nf++) {
        int cb = col0 + wn * 32 + nf * 8 + 2 * tt;
        float bv0 = bias ? bias[cb] : 0.f;
        float bv1 = bias ? bias[cb + 1] : 0.f;
        size_t i0 = (size_t)r0 * Hout + cb;
        size_t i1 = (size_t)r1 * Hout + cb;
        float v00 = c[nf][0] + bv0, v01 = c[nf][1] + bv1;
        float v10 = c[nf][2] + bv0, v11 = c[nf][3] + bv1;
        if (add1) {
            float2 a0 = *(const float2*)&add1[i0];
            float2 a1 = *(const float2*)&add1[i1];
            v00 += a0.x; v01 += a0.y; v10 += a1.x; v11 += a1.y;
        }
        *(float2*)&C[i0] = make_float2(v00, v01);
        *(float2*)&C[i1] = make_float2(v10, v11);
    }
}

// ---------------- S[128,128] += A^T @ B over 64-row chunk ----------------
__global__ void k_atb2(const float* __restrict__ A, const float* __restrict__ Bm,
                       float* __restrict__ S) {
    __shared__ float sA[16][128];
    __shared__ float sB[16][128];
    int t = threadIdx.x;
    int jx = t & 15, iy = t >> 4;
    float acc[8][8];
    #pragma unroll
    for (int i = 0; i < 8; i++)
        #pragma unroll
        for (int j = 0; j < 8; j++) acc[i][j] = 0.f;

    int n0 = blockIdx.x * 64;
    for (int st = 0; st < 4; st++) {
        int nb = n0 + st * 16;
        #pragma unroll
        for (int p = 0; p < 2; p++) {
            int idx = t + p * 256;
            int r = idx >> 5, f4 = idx & 31;
            *(float4*)&sA[r][f4 * 4] = *(const float4*)&A[(size_t)(nb + r) * HH + f4 * 4];
            *(float4*)&sB[r][f4 * 4] = *(const float4*)&Bm[(size_t)(nb + r) * HH + f4 * 4];
        }
        __syncthreads();
        #pragma unroll 4
        for (int n = 0; n < 16; n++) {
            float4 a0 = *(float4*)&sA[n][iy * 8];
            float4 a1 = *(float4*)&sA[n][iy * 8 + 4];
            float4 b0 = *(float4*)&sB[n][jx * 8];
            float4 b1 = *(float4*)&sB[n][jx * 8 + 4];
            float av[8] = {a0.x, a0.y, a0.z, a0.w, a1.x, a1.y, a1.z, a1.w};
            float bw[8] = {b0.x, b0.y, b0.z, b0.w, b1.x, b1.y, b1.z, b1.w};
            #pragma unroll
            for (int i = 0; i < 8; i++)
                #pragma unroll
                for (int j = 0; j < 8; j++) acc[i][j] += av[i] * bw[j];
        }
        __syncthreads();
    }

    #pragma unroll
    for (int i = 0; i < 8; i++) {
        float* p = S + (size_t)(iy * 8 + i) * HH + jx * 8;
        red4(p,     acc[i][0], acc[i][1], acc[i][2], acc[i][3]);
        red4(p + 4, acc[i][4], acc[i][5], acc[i][6], acc[i][7]);
    }
}

// ---------------- z = mean + exp(log_std) * eps ----------------
__global__ void k_zcomb(const float* __restrict__ zml, const float* __restrict__ eps,
                        float* __restrict__ z) {
    int i = blockIdx.x * blockDim.x + threadIdx.x;
    int n = i >> 7, c = i & 127;
    z[i] = zml[n * 256 + c] + expf(zml[n * 256 + 128 + c]) * eps[i];
}

// ---------------- host ----------------
extern "C" void kernel_launch(void* const* d_in, const int* in_sizes, int n_in,
                              void* d_out, int out_size) {
    const int*   src   = (const int*)d_in[1];
    const int*   dst   = (const int*)d_in[2];
    const int*   et    = (const int*)d_in[3];
    const float* norm  = (const float*)d_in[4];
    const float* eps   = (const float*)d_in[5];
    const float* emb   = (const float*)d_in[6];   // node_ids = arange(N) -> x0 = embedding
    const float* W0    = (const float*)d_in[7];
    const float* loop0 = (const float*)d_in[8];
    const float* b0    = (const float*)d_in[9];
    const float* W1    = (const float*)d_in[10];
    const float* loop1 = (const float*)d_in[11];
    const float* b1    = (const float*)d_in[12];
    const float* Wz    = (const float*)d_in[13];
    const float* bz    = (const float*)d_in[14];
    const float* Wi    = (const float*)d_in[15];
    const float* bi    = (const float*)d_in[16];
    const float* hbi   = (const float*)d_in[17];
    const float* Wo    = (const float*)d_in[18];
    const float* bo    = (const float*)d_in[19];
    const float* hbo   = (const float*)d_in[20];
    int E = in_sizes[1];

    float *h, *h2, *zml, *z, *U, *h3, *V, *S, *S2;
    cudaGetSymbolAddress((void**)&h,    g_h);
    cudaGetSymbolAddress((void**)&h2,   g_h2);
    cudaGetSymbolAddress((void**)&zml,  g_zml);
    cudaGetSymbolAddress((void**)&z,    g_z);
    cudaGetSymbolAddress((void**)&U,    g_U);
    cudaGetSymbolAddress((void**)&h3,   g_h3);
    cudaGetSymbolAddress((void**)&V,    g_V);
    cudaGetSymbolAddress((void**)&S,    g_S);
    cudaGetSymbolAddress((void**)&S2,   g_S2);

    float* out = (float*)d_out;
    dim3 egrid(ECHUNK, NRELC);
    const int GSMEM = (64 * ASTR + 2 * 128 * BSTR) * 4;   // 169KB
    cudaFuncSetAttribute(k_gemm_tc, cudaFuncAttributeMaxDynamicSharedMemorySize, GSMEM);
    dim3 tg1(NN / 64, 1), tg2(NN / 64, 2);

    // 1-3: counting sort by relation
    k_hist<<<NBLK, 256>>>(et, E);
    k_scan<<<1, 128>>>(E);
    k_scatter<<<NBLK, 256>>>(et, E);

    // 4: h = emb@loop0 + b0        (launch #4: profiled)
    k_gemm_tc<<<tg1, 512, GSMEM>>>(emb, loop0, nullptr, b0, h, 128, 0);
    k_edges_sorted<<<egrid, 256>>>(emb, src, dst, norm, W0, h, 0);

    // layer 1
    k_gemm_tc<<<tg1, 512, GSMEM>>>(h, loop1, nullptr, b1, h2, 128, 1);
    k_edges_sorted<<<egrid, 256>>>(h, src, dst, norm, W1, h2, 1);

    // VAE head
    k_gemm_tc<<<tg2, 512, GSMEM>>>(h2, Wz, nullptr, bz, zml, 256, 0);
    k_zcomb<<<NN * HH / 256, 256>>>(zml, eps, z);

    // decode 1: h3 = z @ (z^T @ (z@Wi + bi + emb)) + hbi
    k_gemm_tc<<<tg1, 512, GSMEM>>>(z, Wi, emb, bi, U, 128, 0);
    k_zero<<<(HH * HH / 4 + 255) / 256, 256>>>((float4*)S, HH * HH / 4);
    k_atb2<<<NN / 64, 256>>>(z, U, S);
    k_gemm_tc<<<tg1, 512, GSMEM>>>(z, S, nullptr, hbi, h3, 128, 0);

    // decode 2: out = h3 @ (h3^T @ (h3@Wo + bo + emb)) + hbo
    k_gemm_tc<<<tg1, 512, GSMEM>>>(h3, Wo, emb, bo, V, 128, 0);
    k_zero<<<(HH * HH / 4 + 255) / 256, 256>>>((float4*)S2, HH * HH / 4);
    k_atb2<<<NN / 64, 256>>>(h3, V, S2);
    k_gemm_tc<<<tg1, 512, GSMEM>>>(h3, S2, nullptr, hbo, out, 128, 0);
}

// round 13
// speedup vs baseline: 1.1042x; 1.0690x over previous
#include <cuda_runtime.h>
#include <math.h>

#define NN 8192
#define HH 128
#define NRELC 90
#define NBB 8
#define SII 16
#define EMAX 131072
#define ECHUNK 16
#define NBLK 128

typedef unsigned long long ull;

// ---------------- scratch (static device globals; no allocation) ----------------
__device__ float g_h[NN * HH];
__device__ float g_h2[NN * HH];
__device__ float g_zml[NN * 2 * HH];
__device__ float g_z[NN * HH];
__device__ float g_U[NN * HH];
__device__ float g_h3[NN * HH];
__device__ float g_V[NN * HH];
__device__ float g_S[HH * HH];
__device__ float g_S2[HH * HH];
__device__ int   g_blkcnt[NBLK * NRELC];
__device__ int   g_blkbase[NBLK * NRELC];
__device__ int   g_off[NRELC + 1];
__device__ int   g_perm[EMAX];

// vectorized fp32 atomic add (sm_90+)
__device__ __forceinline__ void red4(float* p, float a, float b, float c, float d) {
    asm volatile("red.global.add.v4.f32 [%0], {%1,%2,%3,%4};"
                 :: "l"(p), "f"(a), "f"(b), "f"(c), "f"(d) : "memory");
}
__device__ __forceinline__ void fma2(ull& d, ull a, ull b) {
    asm volatile("fma.rn.f32x2 %0, %1, %2, %0;" : "+l"(d) : "l"(a), "l"(b));
}
__device__ __forceinline__ ull pack2(float x) {
    ull r; asm("mov.b64 %0, {%1, %1};" : "=l"(r) : "f"(x)); return r;
}
__device__ __forceinline__ void unpack2(ull v, float& a, float& b) {
    asm("mov.b64 {%0, %1}, %2;" : "=f"(a), "=f"(b) : "l"(v));
}

// ---------------- tf32 helpers ----------------
__device__ __forceinline__ void tf32split(float x, unsigned& hi, unsigned& lo) {
    asm("cvt.rna.tf32.f32 %0, %1;" : "=r"(hi) : "f"(x));
    float l = x - __uint_as_float(hi);
    asm("cvt.rna.tf32.f32 %0, %1;" : "=r"(lo) : "f"(l));
}
__device__ __forceinline__ unsigned tf32cvt(float x) {
    unsigned hi;
    asm("cvt.rna.tf32.f32 %0, %1;" : "=r"(hi) : "f"(x));
    return hi;
}
__device__ __forceinline__ void mma_tf32(float* c, unsigned a0, unsigned a1,
                                         unsigned a2, unsigned a3,
                                         unsigned b0, unsigned b1) {
    asm volatile("mma.sync.aligned.m16n8k8.row.col.f32.tf32.tf32.f32 "
                 "{%0,%1,%2,%3}, {%4,%5,%6,%7}, {%8,%9}, {%0,%1,%2,%3};"
                 : "+f"(c[0]), "+f"(c[1]), "+f"(c[2]), "+f"(c[3])
                 : "r"(a0), "r"(a1), "r"(a2), "r"(a3), "r"(b0), "r"(b1));
}

// ---------------- counting sort pass 1: per-block histogram ----------------
__global__ void k_hist(const int* __restrict__ et, int E) {
    __shared__ int sh[NRELC];
    for (int i = threadIdx.x; i < NRELC; i += blockDim.x) sh[i] = 0;
    __syncthreads();
    int per = (E + NBLK - 1) / NBLK;
    int b0 = blockIdx.x * per, b1 = min(E, b0 + per);
    for (int i = b0 + threadIdx.x; i < b1; i += blockDim.x)
        atomicAdd(&sh[et[i]], 1);
    __syncthreads();
    for (int i = threadIdx.x; i < NRELC; i += blockDim.x)
        g_blkcnt[blockIdx.x * NRELC + i] = sh[i];
}

__global__ void k_scan(int E) {
    __shared__ int stot[NRELC];
    __shared__ int sbase[NRELC];
    int r = threadIdx.x;
    if (r < NRELC) {
        int tot = 0;
        #pragma unroll 4
        for (int b = 0; b < NBLK; b++) tot += g_blkcnt[b * NRELC + r];
        stot[r] = tot;
    }
    __syncthreads();
    if (r < NRELC) {
        int acc = 0;
        for (int i = 0; i < r; i++) acc += stot[i];
        sbase[r] = acc;
        g_off[r] = acc;
        if (r == NRELC - 1) g_off[NRELC] = E;
    }
    __syncthreads();
    if (r < NRELC) {
        int run = sbase[r];
        #pragma unroll 4
        for (int b = 0; b < NBLK; b++) {
            g_blkbase[b * NRELC + r] = run;
            run += g_blkcnt[b * NRELC + r];
        }
    }
}

__global__ void k_scatter(const int* __restrict__ et, int E) {
    __shared__ int sloc[NRELC];
    for (int i = threadIdx.x; i < NRELC; i += blockDim.x)
        sloc[i] = g_blkbase[blockIdx.x * NRELC + i];
    __syncthreads();
    int per = (E + NBLK - 1) / NBLK;
    int b0 = blockIdx.x * per, b1 = min(E, b0 + per);
    for (int i = b0 + threadIdx.x; i < b1; i += blockDim.x) {
        int p = atomicAdd(&sloc[et[i]], 1);
        g_perm[p] = i;
    }
}

// ---------------- zero fill ----------------
__global__ void k_zero(float4* p, int n4) {
    int i = blockIdx.x * blockDim.x + threadIdx.x;
    if (i < n4) p[i] = make_float4(0.f, 0.f, 0.f, 0.f);
}

// ---------------- edge compute core ----------------
__device__ __forceinline__ void edge_do(float4 xv, int d, float nr, int relu_in,
                                        const ull* w01, const ull* w23,
                                        int b, int o0, int lane,
                                        float* __restrict__ acc_out) {
    float4 xr = xv;
    if (relu_in) {
        xr.x = fmaxf(xr.x, 0.f); xr.y = fmaxf(xr.y, 0.f);
        xr.z = fmaxf(xr.z, 0.f); xr.w = fmaxf(xr.w, 0.f);
    }
    ull a01 = 0ull, a23 = 0ull;
    #pragma unroll
    for (int c = 0; c < 4; c++) {
        int sl = b * 4 + c;
        float4 xi;
        xi.x = __shfl_sync(0xffffffffu, xr.x, sl);
        xi.y = __shfl_sync(0xffffffffu, xr.y, sl);
        xi.z = __shfl_sync(0xffffffffu, xr.z, sl);
        xi.w = __shfl_sync(0xffffffffu, xr.w, sl);
        ull p0 = pack2(xi.x), p1 = pack2(xi.y), p2 = pack2(xi.z), p3 = pack2(xi.w);
        fma2(a01, p0, w01[c * 4 + 0]); fma2(a23, p0, w23[c * 4 + 0]);
        fma2(a01, p1, w01[c * 4 + 1]); fma2(a23, p1, w23[c * 4 + 1]);
        fma2(a01, p2, w01[c * 4 + 2]); fma2(a23, p2, w23[c * 4 + 2]);
        fma2(a01, p3, w01[c * 4 + 3]); fma2(a23, p3, w23[c * 4 + 3]);
    }
    float a0, a1, a2, a3;
    unpack2(a01, a0, a1);
    unpack2(a23, a2, a3);
    red4(acc_out + (size_t)d * HH + lane * 4, a0 * nr, a1 * nr, a2 * nr, a3 * nr);
}

// ---------------- RGCN edge messages ----------------
__global__ void __launch_bounds__(256)
k_edges_sorted(const float* __restrict__ x, const int* __restrict__ src,
               const int* __restrict__ dst, const float* __restrict__ norm,
               const float* __restrict__ W, float* __restrict__ acc_out,
               int relu_in) {
    __shared__ float sW[NBB * SII * SII];
    int rel = blockIdx.y;
    const float4* Wr = (const float4*)(W + rel * 2048);
    for (int i = threadIdx.x; i < 512; i += blockDim.x) ((float4*)sW)[i] = Wr[i];
    __syncthreads();

    int lane = threadIdx.x & 31;
    int warp = threadIdx.x >> 5;
    int b  = lane >> 2;
    int o0 = (lane & 3) * 4;

    ull w01[SII], w23[SII];
    #pragma unroll
    for (int i = 0; i < SII; i++) {
        int idx = b * 256 + i * 16 + o0;
        w01[i] = *(const ull*)&sW[idx];
        w23[i] = *(const ull*)&sW[idx + 2];
    }

    int off0 = g_off[rel];
    int len  = g_off[rel + 1] - off0;
    int start = off0 + (int)(((long long)len * blockIdx.x) / ECHUNK);
    int end   = off0 + (int)(((long long)len * (blockIdx.x + 1)) / ECHUNK);
    const int stride = 16;

    int i = start + warp * 2;

    int dA = 0, dB = 0; float nrA = 0.f, nrB = 0.f;
    float4 xvA = make_float4(0.f, 0.f, 0.f, 0.f);
    float4 xvB = xvA;
    if (i < end) {
        int e = g_perm[i];
        int s = src[e];  dA = dst[e];  nrA = norm[e];
        xvA = ((const float4*)(x + (size_t)s * HH))[lane];
    }
    if (i + 1 < end) {
        int e = g_perm[i + 1];
        int s = src[e];  dB = dst[e];  nrB = norm[e];
        xvB = ((const float4*)(x + (size_t)s * HH))[lane];
    }

    while (i < end) {
        int inext = i + stride;
        int dA2 = 0, dB2 = 0; float nrA2 = 0.f, nrB2 = 0.f;
        float4 xvA2 = make_float4(0.f, 0.f, 0.f, 0.f);
        float4 xvB2 = xvA2;
        if (inext < end) {
            int e = g_perm[inext];
            int s = src[e];  dA2 = dst[e];  nrA2 = norm[e];
            xvA2 = ((const float4*)(x + (size_t)s * HH))[lane];
        }
        if (inext + 1 < end) {
            int e = g_perm[inext + 1];
            int s = src[e];  dB2 = dst[e];  nrB2 = norm[e];
            xvB2 = ((const float4*)(x + (size_t)s * HH))[lane];
        }

        edge_do(xvA, dA, nrA, relu_in, w01, w23, b, o0, lane, acc_out);
        if (i + 1 < end)
            edge_do(xvB, dB, nrB, relu_in, w01, w23, b, o0, lane, acc_out);

        i = inext;
        dA = dA2; nrA = nrA2; xvA = xvA2;
        dB = dB2; nrB = nrB2; xvB = xvB2;
    }
}

// ---------------- tf32 TC GEMM, 2-term (A hi/lo corrected, B plain tf32) --------
// C = A@B with A = Ahi + Alo (both tf32), B = tf32(B). Error ~1e-4 rel (B mantissa).
// CTA tile 64 rows x 128 cols; 512 thr, 16 warps (4m x 4n). Whole K in smem.
// smem: sA 64x132 fp32 (33.8KB) + sBhi 128x136 u32 (69.6KB) = 103KB.
#define ASTR 132
#define BSTR 136
__global__ void __launch_bounds__(512)
k_gemm_tc(const float* __restrict__ A, const float* __restrict__ B,
          const float* __restrict__ add1, const float* __restrict__ bias,
          float* __restrict__ C, int Hout, int reluA) {
    extern __shared__ float sm[];
    float*    sA   = sm;                                  // 64*132
    unsigned* sBhi = (unsigned*)(sm + 64 * ASTR);         // 128*136
    int t = threadIdx.x;
    int row0 = blockIdx.x * 64;
    int col0 = blockIdx.y * 128;

    // stage A (64x128 fp32): 4 float4 per thread
    #pragma unroll
    for (int p = 0; p < 4; p++) {
        int idx = t + p * 512;
        int r = idx >> 5, c4 = idx & 31;
        float4 v = *(const float4*)&A[(size_t)(row0 + r) * HH + c4 * 4];
        if (reluA) {
            v.x = fmaxf(v.x, 0.f); v.y = fmaxf(v.y, 0.f);
            v.z = fmaxf(v.z, 0.f); v.w = fmaxf(v.w, 0.f);
        }
        *(float4*)&sA[r * ASTR + c4 * 4] = v;
    }
    // stage B (128x128) as plain tf32: 8 float4 per thread
    #pragma unroll
    for (int p = 0; p < 8; p++) {
        int idx = t + p * 512;
        int r = idx >> 5, c4 = idx & 31;
        float4 v = *(const float4*)&B[(size_t)r * Hout + col0 + c4 * 4];
        uint4 hi;
        hi.x = tf32cvt(v.x); hi.y = tf32cvt(v.y);
        hi.z = tf32cvt(v.z); hi.w = tf32cvt(v.w);
        *(uint4*)&sBhi[r * BSTR + c4 * 4] = hi;
    }
    __syncthreads();

    int lane = t & 31;
    int g = lane >> 2, tt = lane & 3;
    int warp = t >> 5;
    int wm = warp >> 2;      // 0..3  (16 rows each)
    int wn = warp & 3;       // 0..3  (32 cols each)

    float c[4][4];
    #pragma unroll
    for (int i = 0; i < 4; i++)
        #pragma unroll
        for (int j = 0; j < 4; j++) c[i][j] = 0.f;

    const float* pa0 = &sA[(wm * 16 + g) * ASTR];
    const float* pa1 = pa0 + 8 * ASTR;
    int cbase = wn * 32 + g;

    #pragma unroll
    for (int it = 0; it < 16; it++) {
        const int k0 = it * 8;
        unsigned ah[4], al[4];
        tf32split(pa0[k0 + tt],     ah[0], al[0]);
        tf32split(pa1[k0 + tt],     ah[1], al[1]);
        tf32split(pa0[k0 + tt + 4], ah[2], al[2]);
        tf32split(pa1[k0 + tt + 4], ah[3], al[3]);
        #pragma unroll
        for (int nf = 0; nf < 4; nf++) {
            int cn = cbase + nf * 8;
            unsigned bh0 = sBhi[(k0 + tt) * BSTR + cn];
            unsigned bh1 = sBhi[(k0 + tt + 4) * BSTR + cn];
            mma_tf32(c[nf], ah[0], ah[1], ah[2], ah[3], bh0, bh1);
            mma_tf32(c[nf], al[0], al[1], al[2], al[3], bh0, bh1);
        }
    }

    int r0 = row0 + wm * 16 + g;
    int r1 = r0 + 8;
    #pragma unroll
    for (int nf = 0; nf < 4; nf++) {
        int cb = col0 + wn * 32 + nf * 8 + 2 * tt;
        float bv0 = bias ? bias[cb] : 0.f;
        float bv1 = bias ? bias[cb + 1] : 0.f;
        size_t i0 = (size_t)r0 * Hout + cb;
        size_t i1 = (size_t)r1 * Hout + cb;
        float v00 = c[nf][0] + bv0, v01 = c[nf][1] + bv1;
        float v10 = c[nf][2] + bv0, v11 = c[nf][3] + bv1;
        if (add1) {
            float2 a0 = *(const float2*)&add1[i0];
            float2 a1 = *(const float2*)&add1[i1];
            v00 += a0.x; v01 += a0.y; v10 += a1.x; v11 += a1.y;
        }
        *(float2*)&C[i0] = make_float2(v00, v01);
        *(float2*)&C[i1] = make_float2(v10, v11);
    }
}

// ---------------- S[128,128] += A^T @ B over 64-row chunk ----------------
__global__ void k_atb2(const float* __restrict__ A, const float* __restrict__ Bm,
                       float* __restrict__ S) {
    __shared__ float sA[16][128];
    __shared__ float sB[16][128];
    int t = threadIdx.x;
    int jx = t & 15, iy = t >> 4;
    float acc[8][8];
    #pragma unroll
    for (int i = 0; i < 8; i++)
        #pragma unroll
        for (int j = 0; j < 8; j++) acc[i][j] = 0.f;

    int n0 = blockIdx.x * 64;
    for (int st = 0; st < 4; st++) {
        int nb = n0 + st * 16;
        #pragma unroll
        for (int p = 0; p < 2; p++) {
            int idx = t + p * 256;
            int r = idx >> 5, f4 = idx & 31;
            *(float4*)&sA[r][f4 * 4] = *(const float4*)&A[(size_t)(nb + r) * HH + f4 * 4];
            *(float4*)&sB[r][f4 * 4] = *(const float4*)&Bm[(size_t)(nb + r) * HH + f4 * 4];
        }
        __syncthreads();
        #pragma unroll 4
        for (int n = 0; n < 16; n++) {
            float4 a0 = *(float4*)&sA[n][iy * 8];
            float4 a1 = *(float4*)&sA[n][iy * 8 + 4];
            float4 b0 = *(float4*)&sB[n][jx * 8];
            float4 b1 = *(float4*)&sB[n][jx * 8 + 4];
            float av[8] = {a0.x, a0.y, a0.z, a0.w, a1.x, a1.y, a1.z, a1.w};
            float bw[8] = {b0.x, b0.y, b0.z, b0.w, b1.x, b1.y, b1.z, b1.w};
            #pragma unroll
            for (int i = 0; i < 8; i++)
                #pragma unroll
                for (int j = 0; j < 8; j++) acc[i][j] += av[i] * bw[j];
        }
        __syncthreads();
    }

    #pragma unroll
    for (int i = 0; i < 8; i++) {
        float* p = S + (size_t)(iy * 8 + i) * HH + jx * 8;
        red4(p,     acc[i][0], acc[i][1], acc[i][2], acc[i][3]);
        red4(p + 4, acc[i][4], acc[i][5], acc[i][6], acc[i][7]);
    }
}

// ---------------- z = mean + exp(log_std) * eps ----------------
__global__ void k_zcomb(const float* __restrict__ zml, const float* __restrict__ eps,
                        float* __restrict__ z) {
    int i = blockIdx.x * blockDim.x + threadIdx.x;
    int n = i >> 7, c = i & 127;
    z[i] = zml[n * 256 + c] + expf(zml[n * 256 + 128 + c]) * eps[i];
}

// ---------------- host ----------------
extern "C" void kernel_launch(void* const* d_in, const int* in_sizes, int n_in,
                              void* d_out, int out_size) {
    const int*   src   = (const int*)d_in[1];
    const int*   dst   = (const int*)d_in[2];
    const int*   et    = (const int*)d_in[3];
    const float* norm  = (const float*)d_in[4];
    const float* eps   = (const float*)d_in[5];
    const float* emb   = (const float*)d_in[6];   // node_ids = arange(N) -> x0 = embedding
    const float* W0    = (const float*)d_in[7];
    const float* loop0 = (const float*)d_in[8];
    const float* b0    = (const float*)d_in[9];
    const float* W1    = (const float*)d_in[10];
    const float* loop1 = (const float*)d_in[11];
    const float* b1    = (const float*)d_in[12];
    const float* Wz    = (const float*)d_in[13];
    const float* bz    = (const float*)d_in[14];
    const float* Wi    = (const float*)d_in[15];
    const float* bi    = (const float*)d_in[16];
    const float* hbi   = (const float*)d_in[17];
    const float* Wo    = (const float*)d_in[18];
    const float* bo    = (const float*)d_in[19];
    const float* hbo   = (const float*)d_in[20];
    int E = in_sizes[1];

    float *h, *h2, *zml, *z, *U, *h3, *V, *S, *S2;
    cudaGetSymbolAddress((void**)&h,    g_h);
    cudaGetSymbolAddress((void**)&h2,   g_h2);
    cudaGetSymbolAddress((void**)&zml,  g_zml);
    cudaGetSymbolAddress((void**)&z,    g_z);
    cudaGetSymbolAddress((void**)&U,    g_U);
    cudaGetSymbolAddress((void**)&h3,   g_h3);
    cudaGetSymbolAddress((void**)&V,    g_V);
    cudaGetSymbolAddress((void**)&S,    g_S);
    cudaGetSymbolAddress((void**)&S2,   g_S2);

    float* out = (float*)d_out;
    dim3 egrid(ECHUNK, NRELC);
    const int GSMEM = (64 * ASTR + 128 * BSTR) * 4;   // 103424 B
    cudaFuncSetAttribute(k_gemm_tc, cudaFuncAttributeMaxDynamicSharedMemorySize, GSMEM);
    dim3 tg1(NN / 64, 1), tg2(NN / 64, 2);

    // 1-3: counting sort by relation
    k_hist<<<NBLK, 256>>>(et, E);
    k_scan<<<1, 128>>>(E);
    k_scatter<<<NBLK, 256>>>(et, E);

    // 4: h = emb@loop0 + b0        (launch #4: profiled)
    k_gemm_tc<<<tg1, 512, GSMEM>>>(emb, loop0, nullptr, b0, h, 128, 0);
    k_edges_sorted<<<egrid, 256>>>(emb, src, dst, norm, W0, h, 0);

    // layer 1
    k_gemm_tc<<<tg1, 512, GSMEM>>>(h, loop1, nullptr, b1, h2, 128, 1);
    k_edges_sorted<<<egrid, 256>>>(h, src, dst, norm, W1, h2, 1);

    // VAE head
    k_gemm_tc<<<tg2, 512, GSMEM>>>(h2, Wz, nullptr, bz, zml, 256, 0);
    k_zcomb<<<NN * HH / 256, 256>>>(zml, eps, z);

    // decode 1: h3 = z @ (z^T @ (z@Wi + bi + emb)) + hbi
    k_gemm_tc<<<tg1, 512, GSMEM>>>(z, Wi, emb, bi, U, 128, 0);
    k_zero<<<(HH * HH / 4 + 255) / 256, 256>>>((float4*)S, HH * HH / 4);
    k_atb2<<<NN / 64, 256>>>(z, U, S);
    k_gemm_tc<<<tg1, 512, GSMEM>>>(z, S, nullptr, hbi, h3, 128, 0);

    // decode 2: out = h3 @ (h3^T @ (h3@Wo + bo + emb)) + hbo
    k_gemm_tc<<<tg1, 512, GSMEM>>>(h3, Wo, emb, bo, V, 128, 0);
    k_zero<<<(HH * HH / 4 + 255) / 256, 256>>>((float4*)S2, HH * HH / 4);
    k_atb2<<<NN / 64, 256>>>(h3, V, S2);
    k_gemm_tc<<<tg1, 512, GSMEM>>>(h3, S2, nullptr, hbo, out, 128, 0);
}